// round 6
// baseline (speedup 1.0000x reference)
#include <cuda_runtime.h>
#include <cstdint>

#define N_NODES 200000
#define E_CAP   3200000
#define D 64

typedef unsigned long long u64;

// ---------------------------------------------------------------------------
// Scratch (allocation-free rule: __device__ globals)
// ---------------------------------------------------------------------------
__device__ float g_nbr[(size_t)N_NODES * D];      // 51.2 MB
__device__ float g_h1 [(size_t)N_NODES * D];      // 51.2 MB
__device__ int   g_cnt   [N_NODES];
__device__ int   g_rowptr[N_NODES + 1];
__device__ int   g_cursor[N_NODES];
__device__ int2  g_cv    [E_CAP];                 // packed (col, val-bits)

// ---------------------------------------------------------------------------
// L2 residency policies (createpolicy + cache_hint — the supported spelling)
// ---------------------------------------------------------------------------
__device__ __forceinline__ u64 pol_keep() {       // pin in L2
    u64 p;
    asm("createpolicy.fractional.L2::evict_last.b64 %0, 1.0;" : "=l"(p));
    return p;
}
__device__ __forceinline__ u64 pol_stream() {     // stream through L2
    u64 p;
    asm("createpolicy.fractional.L2::evict_first.b64 %0, 1.0;" : "=l"(p));
    return p;
}
__device__ __forceinline__ float2 ld_f2_hint(const float2* p, u64 pol) {
    float2 v;
    asm volatile("ld.global.nc.L2::cache_hint.v2.f32 {%0,%1}, [%2], %3;"
                 : "=f"(v.x), "=f"(v.y) : "l"(p), "l"(pol));
    return v;
}
__device__ __forceinline__ int2 ld_i2_hint(const int2* p, u64 pol) {
    int2 v;
    asm volatile("ld.global.nc.L2::cache_hint.v2.b32 {%0,%1}, [%2], %3;"
                 : "=r"(v.x), "=r"(v.y) : "l"(p), "l"(pol));
    return v;
}
__device__ __forceinline__ float4 ld_f4_hint(const float4* p, u64 pol) {
    float4 v;
    asm volatile("ld.global.nc.L2::cache_hint.v4.f32 {%0,%1,%2,%3}, [%4], %5;"
                 : "=f"(v.x), "=f"(v.y), "=f"(v.z), "=f"(v.w) : "l"(p), "l"(pol));
    return v;
}
__device__ __forceinline__ void st_f2_hint(float2* p, float2 v, u64 pol) {
    asm volatile("st.global.L2::cache_hint.v2.f32 [%0], {%1,%2}, %3;"
                 :: "l"(p), "f"(v.x), "f"(v.y), "l"(pol) : "memory");
}
__device__ __forceinline__ void st_f4_hint(float4* p, float4 v, u64 pol) {
    asm volatile("st.global.L2::cache_hint.v4.f32 [%0], {%1,%2,%3,%4}, %5;"
                 :: "l"(p), "f"(v.x), "f"(v.y), "f"(v.z), "f"(v.w), "l"(pol) : "memory");
}

// ---------------------------------------------------------------------------
// Packed fp32x2 helpers (2 fp32 FMAs / instruction)
// ---------------------------------------------------------------------------
__device__ __forceinline__ void fma2(u64& d, u64 a, u64 b) {
    asm("fma.rn.f32x2 %0, %1, %2, %0;" : "+l"(d) : "l"(a), "l"(b));
}
__device__ __forceinline__ u64 pk2(float lo, float hi) {
    u64 r; asm("mov.b64 %0, {%1, %2};" : "=l"(r) : "f"(lo), "f"(hi)); return r;
}
__device__ __forceinline__ u64 dup2(float x) {
    u64 r; asm("mov.b64 %0, {%1, %1};" : "=l"(r) : "f"(x)); return r;
}
__device__ __forceinline__ float2 upk2(u64 v) {
    float2 f; asm("mov.b64 {%0, %1}, %2;" : "=f"(f.x), "=f"(f.y) : "l"(v)); return f;
}

// ---------------------------------------------------------------------------
// CSR build
// ---------------------------------------------------------------------------
__global__ void zero_int_kernel(int* __restrict__ p, int n) {
    int i = blockIdx.x * blockDim.x + threadIdx.x;
    int stride = gridDim.x * blockDim.x;
    for (; i < n; i += stride) p[i] = 0;
}

__global__ void hist_kernel(const int* __restrict__ rows, int* __restrict__ cnt, int E) {
    int i = blockIdx.x * blockDim.x + threadIdx.x;
    int stride = gridDim.x * blockDim.x;
    for (; i < E; i += stride) atomicAdd(&cnt[__ldg(rows + i)], 1);
}

__global__ void __launch_bounds__(1024)
scan_kernel(const int* __restrict__ cnt, int* __restrict__ rowptr,
            int* __restrict__ cursor, int n) {
    __shared__ int psum[1024];
    int tid = threadIdx.x;
    int per = (n + 1023) >> 10;
    int start = tid * per;
    int end   = start + per; if (end > n) end = n;
    if (start > n) start = n;

    int s = 0;
    for (int i = start; i < end; i++) s += cnt[i];
    psum[tid] = s;
    __syncthreads();
    for (int off = 1; off < 1024; off <<= 1) {
        int t = (tid >= off) ? psum[tid - off] : 0;
        __syncthreads();
        psum[tid] += t;
        __syncthreads();
    }
    int run = psum[tid] - s;
    for (int i = start; i < end; i++) {
        rowptr[i] = run;
        cursor[i] = run;
        run += cnt[i];
    }
    if (tid == 1023) rowptr[n] = psum[1023];
}

__global__ void scatter_kernel(const int*   __restrict__ rows,
                               const int*   __restrict__ cols,
                               const float* __restrict__ vals,
                               int*  __restrict__ cursor,
                               int2* __restrict__ cv, int E) {
    int i = blockIdx.x * blockDim.x + threadIdx.x;
    int stride = gridDim.x * blockDim.x;
    for (; i < E; i += stride) {
        int r   = __ldg(rows + i);
        int pos = atomicAdd(&cursor[r], 1);
        cv[pos] = make_int2(__ldg(cols + i), __float_as_int(__ldg(vals + i)));
    }
}

// ---------------------------------------------------------------------------
// Pull-mode SpMM. Warp per node; lane owns float2 chunk of the 64-float row.
// Edge metadata: one coalesced evict_first LDG.64 per 32 edges, shfl-broadcast.
// Gathers: evict_last policy (pins x in L2), 4 independent chains.
// Output: single evict_first 256B store per node. No atomics.
// ---------------------------------------------------------------------------
__global__ void __launch_bounds__(512)
spmm_pull_kernel(const int*  __restrict__ rowptr,
                 const int2* __restrict__ cv,
                 const float* __restrict__ x,
                 float*       __restrict__ out,
                 int N) {
    int warp = (blockIdx.x * blockDim.x + threadIdx.x) >> 5;
    if (warp >= N) return;
    int lane = threadIdx.x & 31;

    u64 keep   = pol_keep();
    u64 stream = pol_stream();

    int s = __ldg(rowptr + warp);
    int e = __ldg(rowptr + warp + 1);

    const float2* x2 = (const float2*)x;
    float2 acc0 = make_float2(0.f, 0.f);
    float2 acc1 = make_float2(0.f, 0.f);
    float2 acc2 = make_float2(0.f, 0.f);
    float2 acc3 = make_float2(0.f, 0.f);

    for (int base = s; base < e; base += 32) {
        int idx = base + lane;
        int2 c = (idx < e) ? ld_i2_hint(cv + idx, stream) : make_int2(0, 0);
        int m = e - base; if (m > 32) m = 32;

        int j = 0;
        for (; j + 3 < m; j += 4) {
            int col0 = __shfl_sync(0xFFFFFFFFu, c.x, j);
            int vb0  = __shfl_sync(0xFFFFFFFFu, c.y, j);
            int col1 = __shfl_sync(0xFFFFFFFFu, c.x, j + 1);
            int vb1  = __shfl_sync(0xFFFFFFFFu, c.y, j + 1);
            int col2 = __shfl_sync(0xFFFFFFFFu, c.x, j + 2);
            int vb2  = __shfl_sync(0xFFFFFFFFu, c.y, j + 2);
            int col3 = __shfl_sync(0xFFFFFFFFu, c.x, j + 3);
            int vb3  = __shfl_sync(0xFFFFFFFFu, c.y, j + 3);
            float2 g0 = ld_f2_hint(x2 + (long long)col0 * 32 + lane, keep);
            float2 g1 = ld_f2_hint(x2 + (long long)col1 * 32 + lane, keep);
            float2 g2 = ld_f2_hint(x2 + (long long)col2 * 32 + lane, keep);
            float2 g3 = ld_f2_hint(x2 + (long long)col3 * 32 + lane, keep);
            float v0 = __int_as_float(vb0);
            float v1 = __int_as_float(vb1);
            float v2 = __int_as_float(vb2);
            float v3 = __int_as_float(vb3);
            acc0.x += v0 * g0.x;  acc0.y += v0 * g0.y;
            acc1.x += v1 * g1.x;  acc1.y += v1 * g1.y;
            acc2.x += v2 * g2.x;  acc2.y += v2 * g2.y;
            acc3.x += v3 * g3.x;  acc3.y += v3 * g3.y;
        }
        for (; j < m; j++) {
            int col0 = __shfl_sync(0xFFFFFFFFu, c.x, j);
            float v0 = __int_as_float(__shfl_sync(0xFFFFFFFFu, c.y, j));
            float2 g0 = ld_f2_hint(x2 + (long long)col0 * 32 + lane, keep);
            acc0.x += v0 * g0.x;  acc0.y += v0 * g0.y;
        }
    }

    float2 r = make_float2((acc0.x + acc1.x) + (acc2.x + acc3.x),
                           (acc0.y + acc1.y) + (acc2.y + acc3.y));
    st_f2_hint(((float2*)out) + (long long)warp * 32 + lane, r, stream);
}

// ---------------------------------------------------------------------------
// Fused concat + GEMM + bias + ReLU with packed f32x2 FMAs.
// X streams read with evict_first; output stored evict_last when it will be
// the next SpMM's gather table (keep_out=1), else normal.
// ---------------------------------------------------------------------------
#define DB_ROWS 128
#define DB_THREADS 256
#define XPITCH 65
#define DENSE_SMEM ((128*64 + 2*DB_ROWS*XPITCH) * sizeof(float))

__global__ void __launch_bounds__(DB_THREADS)
dense_kernel(const float* __restrict__ Xh,
             const float* __restrict__ Xn,
             const float* __restrict__ W,   // [128][64] row-major
             const float* __restrict__ b,   // [64]
             float*       __restrict__ out, // [N][64]
             int N, int keep_out) {
    extern __shared__ float sm[];
    float*  Ws  = sm;                 // 128*64 floats
    float*  Xs  = sm + 128 * 64;      // [2][DB_ROWS][XPITCH]
    float4* Ws4 = (float4*)Ws;

    int tid  = threadIdx.x;
    int base = blockIdx.x * DB_ROWS;

    u64 keep   = pol_keep();
    u64 stream = pol_stream();

    const float4* Wg = (const float4*)W;
    for (int i = tid; i < 128 * 16; i += DB_THREADS) Ws4[i] = __ldg(Wg + i);

    int nr = N - base; if (nr > DB_ROWS) nr = DB_ROWS;
    for (int i = tid; i < nr * 16; i += DB_THREADS) {
        int r = i >> 4, c4 = i & 15;
        float4 hv = ld_f4_hint(((const float4*)Xh) + (size_t)(base + r) * 16 + c4, stream);
        float4 nv = ld_f4_hint(((const float4*)Xn) + (size_t)(base + r) * 16 + c4, stream);
        float* ph = Xs + r * XPITCH + c4 * 4;
        float* pn = Xs + DB_ROWS * XPITCH + r * XPITCH + c4 * 4;
        ph[0] = hv.x; ph[1] = hv.y; ph[2] = hv.z; ph[3] = hv.w;
        pn[0] = nv.x; pn[1] = nv.y; pn[2] = nv.z; pn[3] = nv.w;
    }
    __syncthreads();

    int q    = tid & 3;     // column quarter
    int slot = tid >> 2;    // rows slot and slot+64

    u64 a0[8], a1[8];
    #pragma unroll
    for (int v = 0; v < 4; v++) {
        float4 bv = __ldg(((const float4*)b) + q * 4 + v);
        a0[2*v]   = pk2(bv.x, bv.y);
        a0[2*v+1] = pk2(bv.z, bv.w);
        a1[2*v]   = a0[2*v];
        a1[2*v+1] = a0[2*v+1];
    }

    const float* xh0 = Xs + slot * XPITCH;
    const float* xh1 = Xs + (slot + 64) * XPITCH;
    const float* xn0 = Xs + DB_ROWS * XPITCH + slot * XPITCH;
    const float* xn1 = Xs + DB_ROWS * XPITCH + (slot + 64) * XPITCH;

    const ulonglong2* Wsp = (const ulonglong2*)Ws;

    #pragma unroll 4
    for (int k = 0; k < 64; k++) {
        u64 h0 = dup2(xh0[k]);
        u64 h1 = dup2(xh1[k]);
        u64 n0 = dup2(xn0[k]);
        u64 n1 = dup2(xn1[k]);
        #pragma unroll
        for (int v = 0; v < 4; v++) {
            ulonglong2 wh = Wsp[k * 16 + q * 4 + v];
            ulonglong2 wn = Wsp[(64 + k) * 16 + q * 4 + v];
            fma2(a0[2*v],   h0, wh.x);  fma2(a0[2*v+1], h0, wh.y);
            fma2(a0[2*v],   n0, wn.x);  fma2(a0[2*v+1], n0, wn.y);
            fma2(a1[2*v],   h1, wh.x);  fma2(a1[2*v+1], h1, wh.y);
            fma2(a1[2*v],   n1, wn.x);  fma2(a1[2*v+1], n1, wn.y);
        }
    }

    float4* out4 = (float4*)out;
    int r0 = base + slot, r1 = base + slot + 64;
    #pragma unroll
    for (int rr = 0; rr < 2; rr++) {
        int r = rr ? r1 : r0;
        u64* a = rr ? a1 : a0;
        if (r < N) {
            #pragma unroll
            for (int v = 0; v < 4; v++) {
                float2 lo = upk2(a[2*v]), hi = upk2(a[2*v+1]);
                float4 t;
                t.x = fmaxf(lo.x, 0.f); t.y = fmaxf(lo.y, 0.f);
                t.z = fmaxf(hi.x, 0.f); t.w = fmaxf(hi.y, 0.f);
                float4* dst = out4 + (size_t)r * 16 + q * 4 + v;
                if (keep_out) st_f4_hint(dst, t, keep);
                else          *dst = t;
            }
        }
    }
}

// ---------------------------------------------------------------------------
extern "C" void kernel_launch(void* const* d_in, const int* in_sizes, int n_in,
                              void* d_out, int out_size) {
    const int*   rows = (const int*)  d_in[0];
    const int*   cols = (const int*)  d_in[1];
    const float* vals = (const float*)d_in[2];
    const float* emb  = (const float*)d_in[3];
    const float* W1   = (const float*)d_in[4];
    const float* b1   = (const float*)d_in[5];
    const float* W2   = (const float*)d_in[6];
    const float* b2   = (const float*)d_in[7];
    float* out = (float*)d_out;

    int E = in_sizes[0];
    int N = in_sizes[3] / D;

    float *nbr, *h1;
    int *cnt, *rowptr, *cursor;
    int2 *cv;
    cudaGetSymbolAddress((void**)&nbr,    g_nbr);
    cudaGetSymbolAddress((void**)&h1,     g_h1);
    cudaGetSymbolAddress((void**)&cnt,    g_cnt);
    cudaGetSymbolAddress((void**)&rowptr, g_rowptr);
    cudaGetSymbolAddress((void**)&cursor, g_cursor);
    cudaGetSymbolAddress((void**)&cv,     g_cv);

    cudaFuncSetAttribute(dense_kernel,
                         cudaFuncAttributeMaxDynamicSharedMemorySize,
                         (int)DENSE_SMEM);

    int eb = (E + 255) / 256;
    int dense_blocks = (N + DB_ROWS - 1) / DB_ROWS;
    int pull_blocks  = (N * 32 + 511) / 512;   // warp per node

    // ---- CSR build (amortized over both layers) ----
    zero_int_kernel<<<(N + 255) / 256, 256>>>(cnt, N);
    hist_kernel   <<<eb, 256>>>(rows, cnt, E);
    scan_kernel   <<<1, 1024>>>(cnt, rowptr, cursor, N);
    scatter_kernel<<<eb, 256>>>(rows, cols, vals, cursor, cv, E);

    // ---- Layer 1 ----
    spmm_pull_kernel<<<pull_blocks, 512>>>(rowptr, cv, emb, nbr, N);
    dense_kernel<<<dense_blocks, DB_THREADS, DENSE_SMEM>>>(emb, nbr, W1, b1, h1, N, 1);

    // ---- Layer 2 ----
    spmm_pull_kernel<<<pull_blocks, 512>>>(rowptr, cv, h1, nbr, N);
    dense_kernel<<<dense_blocks, DB_THREADS, DENSE_SMEM>>>(h1, nbr, W2, b2, out, N, 0);
}

// round 7
// speedup vs baseline: 1.0024x; 1.0024x over previous
#include <cuda_runtime.h>
#include <cstdint>

#define N_NODES 200000
#define E_CAP   3200000
#define D 64

typedef unsigned long long u64;

// ---------------------------------------------------------------------------
// Scratch (allocation-free rule: __device__ globals; zero-initialized at load)
// ---------------------------------------------------------------------------
__device__ float g_nbr[(size_t)N_NODES * D];      // 51.2 MB
__device__ float g_h1 [(size_t)N_NODES * D];      // 51.2 MB
__device__ int   g_cnt   [N_NODES];               // ZERO at entry (invariant)
__device__ int   g_rowptr[N_NODES + 1];
__device__ int   g_cursor[N_NODES];
__device__ int2  g_cv    [E_CAP];                 // packed (col, val-bits)

// ---------------------------------------------------------------------------
// L2 residency policies (neutral so far; kept — zero cost)
// ---------------------------------------------------------------------------
__device__ __forceinline__ u64 pol_keep() {
    u64 p; asm("createpolicy.fractional.L2::evict_last.b64 %0, 1.0;" : "=l"(p)); return p;
}
__device__ __forceinline__ u64 pol_stream() {
    u64 p; asm("createpolicy.fractional.L2::evict_first.b64 %0, 1.0;" : "=l"(p)); return p;
}
__device__ __forceinline__ float2 ld_f2_hint(const float2* p, u64 pol) {
    float2 v;
    asm volatile("ld.global.nc.L2::cache_hint.v2.f32 {%0,%1}, [%2], %3;"
                 : "=f"(v.x), "=f"(v.y) : "l"(p), "l"(pol));
    return v;
}
__device__ __forceinline__ int2 ld_i2_hint(const int2* p, u64 pol) {
    int2 v;
    asm volatile("ld.global.nc.L2::cache_hint.v2.b32 {%0,%1}, [%2], %3;"
                 : "=r"(v.x), "=r"(v.y) : "l"(p), "l"(pol));
    return v;
}
__device__ __forceinline__ float4 ld_f4_hint(const float4* p, u64 pol) {
    float4 v;
    asm volatile("ld.global.nc.L2::cache_hint.v4.f32 {%0,%1,%2,%3}, [%4], %5;"
                 : "=f"(v.x), "=f"(v.y), "=f"(v.z), "=f"(v.w) : "l"(p), "l"(pol));
    return v;
}
__device__ __forceinline__ void st_f2_hint(float2* p, float2 v, u64 pol) {
    asm volatile("st.global.L2::cache_hint.v2.f32 [%0], {%1,%2}, %3;"
                 :: "l"(p), "f"(v.x), "f"(v.y), "l"(pol) : "memory");
}
__device__ __forceinline__ void st_f4_hint(float4* p, float4 v, u64 pol) {
    asm volatile("st.global.L2::cache_hint.v4.f32 [%0], {%1,%2,%3,%4}, %5;"
                 :: "l"(p), "f"(v.x), "f"(v.y), "f"(v.z), "f"(v.w), "l"(pol) : "memory");
}

// ---------------------------------------------------------------------------
// Packed fp32x2 helpers
// ---------------------------------------------------------------------------
__device__ __forceinline__ void fma2(u64& d, u64 a, u64 b) {
    asm("fma.rn.f32x2 %0, %1, %2, %0;" : "+l"(d) : "l"(a), "l"(b));
}
__device__ __forceinline__ u64 pk2(float lo, float hi) {
    u64 r; asm("mov.b64 %0, {%1, %2};" : "=l"(r) : "f"(lo), "f"(hi)); return r;
}
__device__ __forceinline__ u64 dup2(float x) {
    u64 r; asm("mov.b64 %0, {%1, %1};" : "=l"(r) : "f"(x)); return r;
}
__device__ __forceinline__ float2 upk2(u64 v) {
    float2 f; asm("mov.b64 {%0, %1}, %2;" : "=f"(f.x), "=f"(f.y) : "l"(v)); return f;
}

// ---------------------------------------------------------------------------
// CSR build
// ---------------------------------------------------------------------------
__global__ void zero_int_kernel(int* __restrict__ p, int n) {
    int i = blockIdx.x * blockDim.x + threadIdx.x;
    int stride = gridDim.x * blockDim.x;
    for (; i < n; i += stride) p[i] = 0;
}

// 4 edges per thread: 4 independent atomic chains
__global__ void hist_kernel(const int* __restrict__ rows, int* __restrict__ cnt, int E) {
    int t = blockIdx.x * blockDim.x + threadIdx.x;
    int i0 = t * 4;
    if (i0 + 3 < E) {
        int r0 = __ldg(rows + i0),     r1 = __ldg(rows + i0 + 1);
        int r2 = __ldg(rows + i0 + 2), r3 = __ldg(rows + i0 + 3);
        atomicAdd(&cnt[r0], 1); atomicAdd(&cnt[r1], 1);
        atomicAdd(&cnt[r2], 1); atomicAdd(&cnt[r3], 1);
    } else {
        for (int i = i0; i < E; i++) atomicAdd(&cnt[__ldg(rows + i)], 1);
    }
}

__global__ void __launch_bounds__(1024)
scan_kernel(const int* __restrict__ cnt, int* __restrict__ rowptr,
            int* __restrict__ cursor, int n) {
    __shared__ int psum[1024];
    int tid = threadIdx.x;
    int per = (n + 1023) >> 10;
    int start = tid * per;
    int end   = start + per; if (end > n) end = n;
    if (start > n) start = n;

    int s = 0;
    for (int i = start; i < end; i++) s += cnt[i];
    psum[tid] = s;
    __syncthreads();
    for (int off = 1; off < 1024; off <<= 1) {
        int t = (tid >= off) ? psum[tid - off] : 0;
        __syncthreads();
        psum[tid] += t;
        __syncthreads();
    }
    int run = psum[tid] - s;
    for (int i = start; i < end; i++) {
        rowptr[i] = run;
        cursor[i] = run;
        run += cnt[i];
    }
    if (tid == 1023) rowptr[n] = psum[1023];
}

// 4 edges per thread: 4 independent ATOMG+ST chains
__global__ void scatter_kernel(const int*   __restrict__ rows,
                               const int*   __restrict__ cols,
                               const float* __restrict__ vals,
                               int*  __restrict__ cursor,
                               int2* __restrict__ cv, int E) {
    int t = blockIdx.x * blockDim.x + threadIdx.x;
    int i0 = t * 4;
    if (i0 + 3 < E) {
        int r0 = __ldg(rows + i0),     r1 = __ldg(rows + i0 + 1);
        int r2 = __ldg(rows + i0 + 2), r3 = __ldg(rows + i0 + 3);
        int c0 = __ldg(cols + i0),     c1 = __ldg(cols + i0 + 1);
        int c2 = __ldg(cols + i0 + 2), c3 = __ldg(cols + i0 + 3);
        float v0 = __ldg(vals + i0),     v1 = __ldg(vals + i0 + 1);
        float v2 = __ldg(vals + i0 + 2), v3 = __ldg(vals + i0 + 3);
        int p0 = atomicAdd(&cursor[r0], 1);
        int p1 = atomicAdd(&cursor[r1], 1);
        int p2 = atomicAdd(&cursor[r2], 1);
        int p3 = atomicAdd(&cursor[r3], 1);
        cv[p0] = make_int2(c0, __float_as_int(v0));
        cv[p1] = make_int2(c1, __float_as_int(v1));
        cv[p2] = make_int2(c2, __float_as_int(v2));
        cv[p3] = make_int2(c3, __float_as_int(v3));
    } else {
        for (int i = i0; i < E; i++) {
            int r   = __ldg(rows + i);
            int pos = atomicAdd(&cursor[r], 1);
            cv[pos] = make_int2(__ldg(cols + i), __float_as_int(__ldg(vals + i)));
        }
    }
}

// ---------------------------------------------------------------------------
// Pull-mode SpMM. Warp per node; lane owns float2 chunk of the 64-float row.
// 8-wide predicated unroll: ALWAYS 8 gathers in flight (tail slots re-gather
// the last edge's row with v=0 — hot lines, ~free). No scalar tail.
// ---------------------------------------------------------------------------
__global__ void __launch_bounds__(256)
spmm_pull_kernel(const int*  __restrict__ rowptr,
                 const int2* __restrict__ cv,
                 const float* __restrict__ x,
                 float*       __restrict__ out,
                 int N) {
    int warp = (blockIdx.x * blockDim.x + threadIdx.x) >> 5;
    if (warp >= N) return;
    int lane = threadIdx.x & 31;

    u64 keep   = pol_keep();
    u64 stream = pol_stream();

    int s = __ldg(rowptr + warp);
    int e = __ldg(rowptr + warp + 1);

    const float2* x2 = (const float2*)x;
    float2 acc0 = make_float2(0.f, 0.f);
    float2 acc1 = make_float2(0.f, 0.f);
    float2 acc2 = make_float2(0.f, 0.f);
    float2 acc3 = make_float2(0.f, 0.f);

    for (int base = s; base < e; base += 32) {
        int m = e - base; if (m > 32) m = 32;      // m >= 1
        int idx = base + lane; if (idx >= e) idx = e - 1;
        int2 c = ld_i2_hint(cv + idx, stream);

        for (int j = 0; j < m; j += 8) {
            int   col[8];
            float val[8];
            #pragma unroll
            for (int k = 0; k < 8; k++) {
                int jk = j + k;
                int sl = jk < m ? jk : m - 1;      // clamp -> duplicate hot row
                col[k] = __shfl_sync(0xFFFFFFFFu, c.x, sl);
                float v = __int_as_float(__shfl_sync(0xFFFFFFFFu, c.y, sl));
                val[k] = (jk < m) ? v : 0.f;
            }
            float2 g[8];
            #pragma unroll
            for (int k = 0; k < 8; k++)
                g[k] = ld_f2_hint(x2 + (long long)col[k] * 32 + lane, keep);
            #pragma unroll
            for (int k = 0; k < 8; k++) {
                float2* a = (k & 3) == 0 ? &acc0 : (k & 3) == 1 ? &acc1
                          : (k & 3) == 2 ? &acc2 : &acc3;
                a->x += val[k] * g[k].x;
                a->y += val[k] * g[k].y;
            }
        }
    }

    float2 r = make_float2((acc0.x + acc1.x) + (acc2.x + acc3.x),
                           (acc0.y + acc1.y) + (acc2.y + acc3.y));
    st_f2_hint(((float2*)out) + (long long)warp * 32 + lane, r, stream);
}

// ---------------------------------------------------------------------------
// Fused concat + GEMM + bias + ReLU with packed f32x2 FMAs (unchanged).
// ---------------------------------------------------------------------------
#define DB_ROWS 128
#define DB_THREADS 256
#define XPITCH 65
#define DENSE_SMEM ((128*64 + 2*DB_ROWS*XPITCH) * sizeof(float))

__global__ void __launch_bounds__(DB_THREADS)
dense_kernel(const float* __restrict__ Xh,
             const float* __restrict__ Xn,
             const float* __restrict__ W,   // [128][64] row-major
             const float* __restrict__ b,   // [64]
             float*       __restrict__ out, // [N][64]
             int N, int keep_out) {
    extern __shared__ float sm[];
    float*  Ws  = sm;
    float*  Xs  = sm + 128 * 64;
    float4* Ws4 = (float4*)Ws;

    int tid  = threadIdx.x;
    int base = blockIdx.x * DB_ROWS;

    u64 keep   = pol_keep();
    u64 stream = pol_stream();

    const float4* Wg = (const float4*)W;
    for (int i = tid; i < 128 * 16; i += DB_THREADS) Ws4[i] = __ldg(Wg + i);

    int nr = N - base; if (nr > DB_ROWS) nr = DB_ROWS;
    for (int i = tid; i < nr * 16; i += DB_THREADS) {
        int r = i >> 4, c4 = i & 15;
        float4 hv = ld_f4_hint(((const float4*)Xh) + (size_t)(base + r) * 16 + c4, stream);
        float4 nv = ld_f4_hint(((const float4*)Xn) + (size_t)(base + r) * 16 + c4, stream);
        float* ph = Xs + r * XPITCH + c4 * 4;
        float* pn = Xs + DB_ROWS * XPITCH + r * XPITCH + c4 * 4;
        ph[0] = hv.x; ph[1] = hv.y; ph[2] = hv.z; ph[3] = hv.w;
        pn[0] = nv.x; pn[1] = nv.y; pn[2] = nv.z; pn[3] = nv.w;
    }
    __syncthreads();

    int q    = tid & 3;
    int slot = tid >> 2;

    u64 a0[8], a1[8];
    #pragma unroll
    for (int v = 0; v < 4; v++) {
        float4 bv = __ldg(((const float4*)b) + q * 4 + v);
        a0[2*v]   = pk2(bv.x, bv.y);
        a0[2*v+1] = pk2(bv.z, bv.w);
        a1[2*v]   = a0[2*v];
        a1[2*v+1] = a0[2*v+1];
    }

    const float* xh0 = Xs + slot * XPITCH;
    const float* xh1 = Xs + (slot + 64) * XPITCH;
    const float* xn0 = Xs + DB_ROWS * XPITCH + slot * XPITCH;
    const float* xn1 = Xs + DB_ROWS * XPITCH + (slot + 64) * XPITCH;

    const ulonglong2* Wsp = (const ulonglong2*)Ws;

    #pragma unroll 4
    for (int k = 0; k < 64; k++) {
        u64 h0 = dup2(xh0[k]);
        u64 h1 = dup2(xh1[k]);
        u64 n0 = dup2(xn0[k]);
        u64 n1 = dup2(xn1[k]);
        #pragma unroll
        for (int v = 0; v < 4; v++) {
            ulonglong2 wh = Wsp[k * 16 + q * 4 + v];
            ulonglong2 wn = Wsp[(64 + k) * 16 + q * 4 + v];
            fma2(a0[2*v],   h0, wh.x);  fma2(a0[2*v+1], h0, wh.y);
            fma2(a0[2*v],   n0, wn.x);  fma2(a0[2*v+1], n0, wn.y);
            fma2(a1[2*v],   h1, wh.x);  fma2(a1[2*v+1], h1, wh.y);
            fma2(a1[2*v],   n1, wn.x);  fma2(a1[2*v+1], n1, wn.y);
        }
    }

    float4* out4 = (float4*)out;
    int r0 = base + slot, r1 = base + slot + 64;
    #pragma unroll
    for (int rr = 0; rr < 2; rr++) {
        int r = rr ? r1 : r0;
        u64* a = rr ? a1 : a0;
        if (r < N) {
            #pragma unroll
            for (int v = 0; v < 4; v++) {
                float2 lo = upk2(a[2*v]), hi = upk2(a[2*v+1]);
                float4 t;
                t.x = fmaxf(lo.x, 0.f); t.y = fmaxf(lo.y, 0.f);
                t.z = fmaxf(hi.x, 0.f); t.w = fmaxf(hi.y, 0.f);
                float4* dst = out4 + (size_t)r * 16 + q * 4 + v;
                if (keep_out) st_f4_hint(dst, t, keep);
                else          *dst = t;
            }
        }
    }
}

// ---------------------------------------------------------------------------
// Launch order: hist(1) scan(2) scatter(3) spmm1(4=ncu capture slot) dense1
// spmm2 dense2 zero_cnt(tail). g_cnt starts zeroed (static init) and every
// call re-zeroes it at the end -> invariant holds for every sequential call.
// ---------------------------------------------------------------------------
extern "C" void kernel_launch(void* const* d_in, const int* in_sizes, int n_in,
                              void* d_out, int out_size) {
    const int*   rows = (const int*)  d_in[0];
    const int*   cols = (const int*)  d_in[1];
    const float* vals = (const float*)d_in[2];
    const float* emb  = (const float*)d_in[3];
    const float* W1   = (const float*)d_in[4];
    const float* b1   = (const float*)d_in[5];
    const float* W2   = (const float*)d_in[6];
    const float* b2   = (const float*)d_in[7];
    float* out = (float*)d_out;

    int E = in_sizes[0];
    int N = in_sizes[3] / D;

    float *nbr, *h1;
    int *cnt, *rowptr, *cursor;
    int2 *cv;
    cudaGetSymbolAddress((void**)&nbr,    g_nbr);
    cudaGetSymbolAddress((void**)&h1,     g_h1);
    cudaGetSymbolAddress((void**)&cnt,    g_cnt);
    cudaGetSymbolAddress((void**)&rowptr, g_rowptr);
    cudaGetSymbolAddress((void**)&cursor, g_cursor);
    cudaGetSymbolAddress((void**)&cv,     g_cv);

    cudaFuncSetAttribute(dense_kernel,
                         cudaFuncAttributeMaxDynamicSharedMemorySize,
                         (int)DENSE_SMEM);

    int eb4 = (E + 4 * 256 - 1) / (4 * 256);       // 4 edges/thread
    int dense_blocks = (N + DB_ROWS - 1) / DB_ROWS;
    int pull_blocks  = (N * 32 + 255) / 256;        // warp per node

    // ---- CSR build (cnt is pre-zeroed by invariant) ----
    hist_kernel   <<<eb4, 256>>>(rows, cnt, E);
    scan_kernel   <<<1, 1024>>>(cnt, rowptr, cursor, N);
    scatter_kernel<<<eb4, 256>>>(rows, cols, vals, cursor, cv, E);

    // ---- Layer 1 ----
    spmm_pull_kernel<<<pull_blocks, 256>>>(rowptr, cv, emb, nbr, N);
    dense_kernel<<<dense_blocks, DB_THREADS, DENSE_SMEM>>>(emb, nbr, W1, b1, h1, N, 1);

    // ---- Layer 2 ----
    spmm_pull_kernel<<<pull_blocks, 256>>>(rowptr, cv, h1, nbr, N);
    dense_kernel<<<dense_blocks, DB_THREADS, DENSE_SMEM>>>(h1, nbr, W2, b2, out, N, 0);

    // ---- restore invariant for next call ----
    zero_int_kernel<<<(N + 255) / 256, 256>>>(cnt, N);
}

// round 8
// speedup vs baseline: 1.1051x; 1.1025x over previous
#include <cuda_runtime.h>
#include <cstdint>

#define N_NODES 200000
#define E_CAP   3200000
#define D 64

typedef unsigned long long u64;

// ---------------------------------------------------------------------------
// Scratch (allocation-free rule: __device__ globals; zero-initialized at load)
// ---------------------------------------------------------------------------
__device__ float g_h1 [(size_t)N_NODES * D];      // 51.2 MB intermediate
__device__ int   g_cnt   [N_NODES];               // ZERO at entry (invariant)
__device__ int   g_rowptr[N_NODES + 1];
__device__ int   g_cursor[N_NODES];
__device__ int2  g_cv    [E_CAP];                 // packed (col, val-bits)

// ---------------------------------------------------------------------------
// L2 residency policies
// ---------------------------------------------------------------------------
__device__ __forceinline__ u64 pol_keep() {
    u64 p; asm("createpolicy.fractional.L2::evict_last.b64 %0, 1.0;" : "=l"(p)); return p;
}
__device__ __forceinline__ u64 pol_stream() {
    u64 p; asm("createpolicy.fractional.L2::evict_first.b64 %0, 1.0;" : "=l"(p)); return p;
}
__device__ __forceinline__ float2 ld_f2_hint(const float2* p, u64 pol) {
    float2 v;
    asm volatile("ld.global.nc.L2::cache_hint.v2.f32 {%0,%1}, [%2], %3;"
                 : "=f"(v.x), "=f"(v.y) : "l"(p), "l"(pol));
    return v;
}
__device__ __forceinline__ int2 ld_i2_hint(const int2* p, u64 pol) {
    int2 v;
    asm volatile("ld.global.nc.L2::cache_hint.v2.b32 {%0,%1}, [%2], %3;"
                 : "=r"(v.x), "=r"(v.y) : "l"(p), "l"(pol));
    return v;
}
__device__ __forceinline__ void st_f2_hint(float2* p, float2 v, u64 pol) {
    asm volatile("st.global.L2::cache_hint.v2.f32 [%0], {%1,%2}, %3;"
                 :: "l"(p), "f"(v.x), "f"(v.y), "l"(pol) : "memory");
}

// ---------------------------------------------------------------------------
// Packed fp32x2 helpers
// ---------------------------------------------------------------------------
__device__ __forceinline__ void fma2(u64& d, u64 a, u64 b) {
    asm("fma.rn.f32x2 %0, %1, %2, %0;" : "+l"(d) : "l"(a), "l"(b));
}
__device__ __forceinline__ u64 dup2(float x) {
    u64 r; asm("mov.b64 %0, {%1, %1};" : "=l"(r) : "f"(x)); return r;
}
__device__ __forceinline__ float2 upk2(u64 v) {
    float2 f; asm("mov.b64 {%0, %1}, %2;" : "=f"(f.x), "=f"(f.y) : "l"(v)); return f;
}

// ---------------------------------------------------------------------------
// CSR build (unchanged from R7)
// ---------------------------------------------------------------------------
__global__ void zero_int_kernel(int* __restrict__ p, int n) {
    int i = blockIdx.x * blockDim.x + threadIdx.x;
    int stride = gridDim.x * blockDim.x;
    for (; i < n; i += stride) p[i] = 0;
}

__global__ void hist_kernel(const int* __restrict__ rows, int* __restrict__ cnt, int E) {
    int t = blockIdx.x * blockDim.x + threadIdx.x;
    int i0 = t * 4;
    if (i0 + 3 < E) {
        int r0 = __ldg(rows + i0),     r1 = __ldg(rows + i0 + 1);
        int r2 = __ldg(rows + i0 + 2), r3 = __ldg(rows + i0 + 3);
        atomicAdd(&cnt[r0], 1); atomicAdd(&cnt[r1], 1);
        atomicAdd(&cnt[r2], 1); atomicAdd(&cnt[r3], 1);
    } else {
        for (int i = i0; i < E; i++) atomicAdd(&cnt[__ldg(rows + i)], 1);
    }
}

__global__ void __launch_bounds__(1024)
scan_kernel(const int* __restrict__ cnt, int* __restrict__ rowptr,
            int* __restrict__ cursor, int n) {
    __shared__ int psum[1024];
    int tid = threadIdx.x;
    int per = (n + 1023) >> 10;
    int start = tid * per;
    int end   = start + per; if (end > n) end = n;
    if (start > n) start = n;

    int s = 0;
    for (int i = start; i < end; i++) s += cnt[i];
    psum[tid] = s;
    __syncthreads();
    for (int off = 1; off < 1024; off <<= 1) {
        int t = (tid >= off) ? psum[tid - off] : 0;
        __syncthreads();
        psum[tid] += t;
        __syncthreads();
    }
    int run = psum[tid] - s;
    for (int i = start; i < end; i++) {
        rowptr[i] = run;
        cursor[i] = run;
        run += cnt[i];
    }
    if (tid == 1023) rowptr[n] = psum[1023];
}

__global__ void scatter_kernel(const int*   __restrict__ rows,
                               const int*   __restrict__ cols,
                               const float* __restrict__ vals,
                               int*  __restrict__ cursor,
                               int2* __restrict__ cv, int E) {
    int t = blockIdx.x * blockDim.x + threadIdx.x;
    int i0 = t * 4;
    if (i0 + 3 < E) {
        int r0 = __ldg(rows + i0),     r1 = __ldg(rows + i0 + 1);
        int r2 = __ldg(rows + i0 + 2), r3 = __ldg(rows + i0 + 3);
        int c0 = __ldg(cols + i0),     c1 = __ldg(cols + i0 + 1);
        int c2 = __ldg(cols + i0 + 2), c3 = __ldg(cols + i0 + 3);
        float v0 = __ldg(vals + i0),     v1 = __ldg(vals + i0 + 1);
        float v2 = __ldg(vals + i0 + 2), v3 = __ldg(vals + i0 + 3);
        int p0 = atomicAdd(&cursor[r0], 1);
        int p1 = atomicAdd(&cursor[r1], 1);
        int p2 = atomicAdd(&cursor[r2], 1);
        int p3 = atomicAdd(&cursor[r3], 1);
        cv[p0] = make_int2(c0, __float_as_int(v0));
        cv[p1] = make_int2(c1, __float_as_int(v1));
        cv[p2] = make_int2(c2, __float_as_int(v2));
        cv[p3] = make_int2(c3, __float_as_int(v3));
    } else {
        for (int i = i0; i < E; i++) {
            int r   = __ldg(rows + i);
            int pos = atomicAdd(&cursor[r], 1);
            cv[pos] = make_int2(__ldg(cols + i), __float_as_int(__ldg(vals + i)));
        }
    }
}

// ---------------------------------------------------------------------------
// In-warp SpMM for one node: returns this lane's float2 chunk of nbr row.
// Batched metadata (1 coalesced LDG.64 per 32 edges) + shfl broadcast,
// 4 independent gather chains, clamp-predicated (no scalar tail).
// ---------------------------------------------------------------------------
__device__ __forceinline__ float2 spmm_row(const int*  __restrict__ rowptr,
                                           const int2* __restrict__ cv,
                                           const float2* __restrict__ x2,
                                           int node, int lane,
                                           u64 keep, u64 stream) {
    int s = __ldg(rowptr + node);
    int e = __ldg(rowptr + node + 1);

    float2 a0 = make_float2(0.f, 0.f), a1 = a0, a2 = a0, a3 = a0;

    for (int base = s; base < e; base += 32) {
        int m = e - base; if (m > 32) m = 32;          // m >= 1
        int idx = base + lane; if (idx >= e) idx = e - 1;
        int2 c = ld_i2_hint(cv + idx, stream);

        for (int j = 0; j < m; j += 4) {
            int   col[4];
            float val[4];
            #pragma unroll
            for (int k = 0; k < 4; k++) {
                int jk = j + k;
                int sl = jk < m ? jk : m - 1;          // clamp -> hot dup line
                col[k] = __shfl_sync(0xFFFFFFFFu, c.x, sl);
                float v = __int_as_float(__shfl_sync(0xFFFFFFFFu, c.y, sl));
                val[k] = (jk < m) ? v : 0.f;
            }
            float2 g[4];
            #pragma unroll
            for (int k = 0; k < 4; k++)
                g[k] = ld_f2_hint(x2 + (long long)col[k] * 32 + lane, keep);
            a0.x += val[0] * g[0].x;  a0.y += val[0] * g[0].y;
            a1.x += val[1] * g[1].x;  a1.y += val[1] * g[1].y;
            a2.x += val[2] * g[2].x;  a2.y += val[2] * g[2].y;
            a3.x += val[3] * g[3].x;  a3.y += val[3] * g[3].y;
        }
    }
    return make_float2((a0.x + a1.x) + (a2.x + a3.x),
                       (a0.y + a1.y) + (a2.y + a3.y));
}

// ---------------------------------------------------------------------------
// FUSED layer: out[n] = relu(b + concat(h[n], spmm(n)) @ W)
// Block = 256 threads (8 warps); warp handles 2 nodes.
// W (128x64, 32KB) staged once per block in smem; GEMM done in-warp:
// shfl-broadcast comb values, LDS.64 W pairs (amortized over 2 nodes), fma2.
// nbr is never materialized in global memory.
// ---------------------------------------------------------------------------
__global__ void __launch_bounds__(256)
fused_layer_kernel(const int*  __restrict__ rowptr,
                   const int2* __restrict__ cv,
                   const float* __restrict__ x,    // [N][64] node features
                   const float* __restrict__ W,    // [128][64] row-major
                   const float* __restrict__ b,    // [64]
                   float*       __restrict__ out,  // [N][64]
                   int N, int keep_out) {
    __shared__ float Ws[128 * 64];
    __shared__ float bs[64];

    int tid = threadIdx.x;
    const float4* Wg  = (const float4*)W;
    float4*       Ws4 = (float4*)Ws;
    #pragma unroll
    for (int i = 0; i < 8; i++) Ws4[tid + i * 256] = __ldg(Wg + tid + i * 256);
    if (tid < 16) ((float4*)bs)[tid] = __ldg(((const float4*)b) + tid);
    __syncthreads();

    int wid = tid >> 5, lane = tid & 31;
    int n0 = (blockIdx.x * 8 + wid) * 2;
    if (n0 >= N) return;                      // warp-uniform
    int n1 = n0 + 1;
    bool has1 = (n1 < N);                     // warp-uniform

    u64 keep = pol_keep(), stream = pol_stream();
    const float2* x2 = (const float2*)x;

    // --- SpMM both nodes (registers only) ---
    float2 A = spmm_row(rowptr, cv, x2, n0, lane, keep, stream);
    float2 B = has1 ? spmm_row(rowptr, cv, x2, n1, lane, keep, stream)
                    : make_float2(0.f, 0.f);

    // --- self rows ---
    float2 hA = ld_f2_hint(x2 + (long long)n0 * 32 + lane, keep);
    float2 hB = has1 ? ld_f2_hint(x2 + (long long)n1 * 32 + lane, keep)
                     : make_float2(0.f, 0.f);

    // --- GEMM: lane computes output cols (2*lane, 2*lane+1) for both nodes ---
    u64 oA = *(const u64*)&bs[2 * lane];
    u64 oB = oA;

    #pragma unroll 4
    for (int sl = 0; sl < 32; sl++) {
        float hax = __shfl_sync(0xFFFFFFFFu, hA.x, sl);
        float hay = __shfl_sync(0xFFFFFFFFu, hA.y, sl);
        float aax = __shfl_sync(0xFFFFFFFFu, A.x,  sl);
        float aay = __shfl_sync(0xFFFFFFFFu, A.y,  sl);
        float hbx = __shfl_sync(0xFFFFFFFFu, hB.x, sl);
        float hby = __shfl_sync(0xFFFFFFFFu, hB.y, sl);
        float abx = __shfl_sync(0xFFFFFFFFu, B.x,  sl);
        float aby = __shfl_sync(0xFFFFFFFFu, B.y,  sl);

        u64 w0 = *(const u64*)&Ws[(2 * sl)      * 64 + 2 * lane];
        u64 w1 = *(const u64*)&Ws[(2 * sl + 1)  * 64 + 2 * lane];
        u64 w2 = *(const u64*)&Ws[(64 + 2 * sl) * 64 + 2 * lane];
        u64 w3 = *(const u64*)&Ws[(65 + 2 * sl) * 64 + 2 * lane];

        fma2(oA, dup2(hax), w0);  fma2(oA, dup2(hay), w1);
        fma2(oA, dup2(aax), w2);  fma2(oA, dup2(aay), w3);
        fma2(oB, dup2(hbx), w0);  fma2(oB, dup2(hby), w1);
        fma2(oB, dup2(abx), w2);  fma2(oB, dup2(aby), w3);
    }

    u64 opol = keep_out ? keep : stream;
    float2* o2 = (float2*)out;
    {
        float2 r = upk2(oA);
        r.x = fmaxf(r.x, 0.f); r.y = fmaxf(r.y, 0.f);
        st_f2_hint(o2 + (long long)n0 * 32 + lane, r, opol);
    }
    if (has1) {
        float2 r = upk2(oB);
        r.x = fmaxf(r.x, 0.f); r.y = fmaxf(r.y, 0.f);
        st_f2_hint(o2 + (long long)n1 * 32 + lane, r, opol);
    }
}

// ---------------------------------------------------------------------------
// Launch order: hist(1) scan(2) scatter(3) fused1(4=ncu slot) fused2(5)
// zero_cnt(tail). g_cnt zero-at-entry invariant maintained.
// ---------------------------------------------------------------------------
extern "C" void kernel_launch(void* const* d_in, const int* in_sizes, int n_in,
                              void* d_out, int out_size) {
    const int*   rows = (const int*)  d_in[0];
    const int*   cols = (const int*)  d_in[1];
    const float* vals = (const float*)d_in[2];
    const float* emb  = (const float*)d_in[3];
    const float* W1   = (const float*)d_in[4];
    const float* b1   = (const float*)d_in[5];
    const float* W2   = (const float*)d_in[6];
    const float* b2   = (const float*)d_in[7];
    float* out = (float*)d_out;

    int E = in_sizes[0];
    int N = in_sizes[3] / D;

    float *h1;
    int *cnt, *rowptr, *cursor;
    int2 *cv;
    cudaGetSymbolAddress((void**)&h1,     g_h1);
    cudaGetSymbolAddress((void**)&cnt,    g_cnt);
    cudaGetSymbolAddress((void**)&rowptr, g_rowptr);
    cudaGetSymbolAddress((void**)&cursor, g_cursor);
    cudaGetSymbolAddress((void**)&cv,     g_cv);

    int eb4 = (E + 4 * 256 - 1) / (4 * 256);
    int fused_blocks = (N + 15) / 16;              // 8 warps x 2 nodes per block

    // ---- CSR build (cnt pre-zeroed by invariant) ----
    hist_kernel   <<<eb4, 256>>>(rows, cnt, E);
    scan_kernel   <<<1, 1024>>>(cnt, rowptr, cursor, N);
    scatter_kernel<<<eb4, 256>>>(rows, cols, vals, cursor, cv, E);

    // ---- Layer 1 (fused spmm+concat+gemm+relu) ----
    fused_layer_kernel<<<fused_blocks, 256>>>(rowptr, cv, emb, W1, b1, h1, N, 1);

    // ---- Layer 2 ----
    fused_layer_kernel<<<fused_blocks, 256>>>(rowptr, cv, h1, W2, b2, out, N, 0);

    // ---- restore invariant ----
    zero_int_kernel<<<(N + 255) / 256, 256>>>(cnt, N);
}